// round 1
// baseline (speedup 1.0000x reference)
#include <cuda_runtime.h>

// out[b, f, s] = x[b, 0, s] * w[f, s] + bias[f, s]
// B=128, F=256, S=4096. Pure HBM-store-bound: 512 MiB out.

#define BATCH 128
#define NFILT 256
#define SLEN  4096

// One block per (b, f) row. 256 threads, each handles 4 float4 = 16 floats.
// 256 * 16 = 4096 = SLEN.
__global__ __launch_bounds__(256) void dense_filter_expand_kernel(
    const float4* __restrict__ x,     // [B, S/4]
    const float4* __restrict__ w,     // [F, S/4]
    const float4* __restrict__ bias,  // [F, S/4]
    float4* __restrict__ out)         // [B, F, S/4]
{
    const int S4 = SLEN / 4;                 // 1024 float4 per row
    int f = blockIdx.x;                      // 0..255
    int b = blockIdx.y;                      // 0..127

    const float4* xr = x    + (size_t)b * S4;
    const float4* wr = w    + (size_t)f * S4;
    const float4* br = bias + (size_t)f * S4;
    float4*       orow = out + ((size_t)b * NFILT + f) * S4;

    int t = threadIdx.x;
#pragma unroll
    for (int i = 0; i < 4; i++) {
        int idx = t + i * 256;               // 0..1023
        float4 xv = xr[idx];
        float4 wv = wr[idx];
        float4 bv = br[idx];
        float4 o;
        o.x = fmaf(xv.x, wv.x, bv.x);
        o.y = fmaf(xv.y, wv.y, bv.y);
        o.z = fmaf(xv.z, wv.z, bv.z);
        o.w = fmaf(xv.w, wv.w, bv.w);
        orow[idx] = o;
    }
}

extern "C" void kernel_launch(void* const* d_in, const int* in_sizes, int n_in,
                              void* d_out, int out_size) {
    const float4* x    = (const float4*)d_in[0];   // inputs [128,1,4096]
    const float4* w    = (const float4*)d_in[1];   // w [256,4096]
    const float4* bias = (const float4*)d_in[2];   // b [256,4096]
    float4* out = (float4*)d_out;

    dim3 grid(NFILT, BATCH);
    dense_filter_expand_kernel<<<grid, 256>>>(x, w, bias, out);
}

// round 2
// speedup vs baseline: 1.1232x; 1.1232x over previous
#include <cuda_runtime.h>

// out[b, f, s] = x[b, 0, s] * w[f, s] + bias[f, s]
// B=128, F=256, S=4096. HBM-store-bound: 512 MiB out, ~10 MiB compulsory reads.
//
// R2: register-cache w[f]/bias[f] per block, loop over 16 batches.
// Read amplification at L1/L2 drops 3.0 -> 1.125 bytes per output byte.

#define BATCH 128
#define NFILT 256
#define SLEN  4096
#define BT    16          // batches per block

__global__ __launch_bounds__(256) void dense_filter_expand_kernel(
    const float4* __restrict__ x,     // [B, S/4]
    const float4* __restrict__ w,     // [F, S/4]
    const float4* __restrict__ bias,  // [F, S/4]
    float4* __restrict__ out)         // [B, F, S/4]
{
    const int S4 = SLEN / 4;                 // 1024 float4 per row
    const int f  = blockIdx.x;               // 0..255  (fastest -> co-resident CTAs share bg)
    const int bg = blockIdx.y;               // 0..7
    const int t  = threadIdx.x;              // 0..255

    // Hold the whole w/bias row for this filter in registers:
    // 4 float4 per thread x 256 threads = 1024 float4 = 4096 floats.
    float4 wv[4], bv[4];
    {
        const float4* wr = w    + (size_t)f * S4;
        const float4* br = bias + (size_t)f * S4;
#pragma unroll
        for (int i = 0; i < 4; i++) {
            wv[i] = wr[t + i * 256];
            bv[i] = br[t + i * 256];
        }
    }

#pragma unroll 1
    for (int bb = 0; bb < BT; bb++) {
        const int b = bg * BT + bb;
        const float4* xr = x + (size_t)b * S4;
        float4* orow = out + ((size_t)b * NFILT + f) * S4;

        float4 xv[4];
#pragma unroll
        for (int i = 0; i < 4; i++)
            xv[i] = xr[t + i * 256];         // 4 independent loads -> MLP=4

#pragma unroll
        for (int i = 0; i < 4; i++) {
            float4 o;
            o.x = fmaf(xv[i].x, wv[i].x, bv[i].x);
            o.y = fmaf(xv[i].y, wv[i].y, bv[i].y);
            o.z = fmaf(xv[i].z, wv[i].z, bv[i].z);
            o.w = fmaf(xv[i].w, wv[i].w, bv[i].w);
            orow[t + i * 256] = o;
        }
    }
}

extern "C" void kernel_launch(void* const* d_in, const int* in_sizes, int n_in,
                              void* d_out, int out_size) {
    const float4* x    = (const float4*)d_in[0];   // inputs [128,1,4096]
    const float4* w    = (const float4*)d_in[1];   // w [256,4096]
    const float4* bias = (const float4*)d_in[2];   // b [256,4096]
    float4* out = (float4*)d_out;

    dim3 grid(NFILT, BATCH / BT);                  // (256, 8)
    dense_filter_expand_kernel<<<grid, 256>>>(x, w, bias, out);
}

// round 3
// speedup vs baseline: 1.2316x; 1.0966x over previous
#include <cuda_runtime.h>

// out[b, f, s] = x[b, 0, s] * w[f, s] + bias[f, s]
// B=128, F=256, S=4096. HBM-store-bound: 512 MiB out.
//
// R3: 2D tile (FT=8 filters x BT=16 batches) per block over a 1024-float
// s-chunk. x register-cached (16 float4/thread), w/bias streamed once per
// filter. Read bytes per write byte: 0.25 (was 1.0).

#define BATCH 128
#define NFILT 256
#define SLEN  4096
#define FT    8           // filters per block
#define BT    16          // batches per block
#define CHUNK4 256        // float4 per s-chunk (1024 floats), one per thread

__global__ __launch_bounds__(256, 2) void dense_filter_expand_kernel(
    const float4* __restrict__ x,     // [B, S/4]
    const float4* __restrict__ w,     // [F, S/4]
    const float4* __restrict__ bias,  // [F, S/4]
    float4* __restrict__ out)         // [B, F, S/4]
{
    const int S4 = SLEN / 4;                   // 1024 float4 per row
    const int t  = threadIdx.x;                // 0..255
    const int sc = blockIdx.x;                 // 0..3   s-chunk
    const int fg = blockIdx.y;                 // 0..31  filter group
    const int bg = blockIdx.z;                 // 0..7   batch group
    const int s4 = sc * CHUNK4 + t;            // float4 index within a row
    const int b0 = bg * BT;
    const int f0 = fg * FT;

    // Register-cache x for the 16 batches in this group (64 regs).
    float4 xv[BT];
#pragma unroll
    for (int i = 0; i < BT; i++)
        xv[i] = __ldg(&x[(size_t)(b0 + i) * S4 + s4]);

#pragma unroll 1
    for (int ff = 0; ff < FT; ff++) {
        const int f = f0 + ff;
        const float4 wv = __ldg(&w[(size_t)f * S4 + s4]);
        const float4 bv = __ldg(&bias[(size_t)f * S4 + s4]);

#pragma unroll
        for (int i = 0; i < BT; i++) {
            float4 o;
            o.x = fmaf(xv[i].x, wv.x, bv.x);
            o.y = fmaf(xv[i].y, wv.y, bv.y);
            o.z = fmaf(xv[i].z, wv.z, bv.z);
            o.w = fmaf(xv[i].w, wv.w, bv.w);
            // Streaming store: output is write-once, never re-read.
            __stcs(&out[((size_t)(b0 + i) * NFILT + f) * S4 + s4], o);
        }
    }
}

extern "C" void kernel_launch(void* const* d_in, const int* in_sizes, int n_in,
                              void* d_out, int out_size) {
    const float4* x    = (const float4*)d_in[0];   // inputs [128,1,4096]
    const float4* w    = (const float4*)d_in[1];   // w [256,4096]
    const float4* bias = (const float4*)d_in[2];   // b [256,4096]
    float4* out = (float4*)d_out;

    dim3 grid(SLEN / (CHUNK4 * 4), NFILT / FT, BATCH / BT);  // (4, 32, 8) = 1024
    dense_filter_expand_kernel<<<grid, 256>>>(x, w, bias, out);
}